// round 5
// baseline (speedup 1.0000x reference)
#include <cuda_runtime.h>

#define NN 50000
#define EE 800000
#define TT 3
#define HH 8
#define D1 64
#define C2 16

// ---------------- scratch (static device globals; no allocation) ----------------
__device__ float g_feat1[NN * TT * D1];   // 38.4 MB per-(node,type) layer0 features
__device__ float g_es1[NN * TT * HH];     // 4.8 MB  exp(leakyrelu(score)) layer0, [n][t][h]
__device__ float g_h[NN * D1];            // 12.8 MB layer0 output
__device__ float g_feat2[NN * TT * C2];   // 9.6 MB
__device__ float g_es2[NN * TT];          // 0.6 MB  [n][t]
__device__ float g_resid[NN * C2];        // 3.2 MB  h@res_w + b
__device__ float g_v1[D1 * TT * HH];      // [i][t*8+h] : W1[t]^T-contracted attention vec
__device__ float g_v2[TT * D1];           // [t][i]
__device__ float g_Wc[D1 * 64];           // combined [W2(t=0..2) | res_w]
__device__ int   g_deg[NN];               // zero at load; re-zeroed by k_scatter tail
__device__ int   g_rowptr[NN + 1];
__device__ int   g_cursor[NN];
__device__ int   g_gather[EE];            // CSR payload: src*3 + etype

#define HIST_BLOCKS ((EE + 1023) / 1024)  // 782, 4 edges/thread

// ---------------- setup: hist + zero d_out + build v1/v2/Wc ----------------
__global__ void k_setup(const float* __restrict__ al1, const float* __restrict__ ar1,
                        const float* __restrict__ al2, const float* __restrict__ ar2,
                        const float* __restrict__ W1, const float* __restrict__ W2,
                        const float* __restrict__ res_w, const int* __restrict__ dst,
                        float* __restrict__ d_out) {
    int b = blockIdx.x;
    int tid = threadIdx.x;
    if (b < HIST_BLOCKS) {  // histogram of dst, 4 independent REDG per thread
        int t0 = b * 1024 + tid;
#pragma unroll
        for (int k = 0; k < 4; k++) {
            int e = t0 + k * 256;
            if (e < EE) atomicAdd(&g_deg[dst[e]], 1);
        }
        return;
    }
    b -= HIST_BLOCKS;
    if (b < TT) {  // v1 for type t=b:  v1[i][h] = sum_c W1[t][i][c] * u1[t][c][h]
        int t = b;
        __shared__ float u1s[64][8];
        for (int e = tid; e < 512; e += 256) {
            int c = e >> 3, h = e & 7;
            const float* pl = al1 + t * 4096 + c * 64 + h * 8;
            const float* pr = ar1 + t * 4096 + c * 64 + h * 8;
            float s = 0.f;
#pragma unroll
            for (int d = 0; d < 8; d++) s += pl[d] + pr[d];
            u1s[c][h] = s;
        }
        __syncthreads();
        for (int e = tid; e < 512; e += 256) {
            int i = e >> 3, h = e & 7;
            const float* w = W1 + t * 4096 + i * 64;
            float s = 0.f;
#pragma unroll 8
            for (int c = 0; c < 64; c++) s = fmaf(w[c], u1s[c][h], s);
            g_v1[i * 24 + t * 8 + h] = s;
        }
        return;
    }
    b -= TT;
    if (b < 1) {  // v2[t][i] = sum_c W2[t][i][c] * u2[t][c]; also zero d_out
        __shared__ float u2s[48];
        if (tid < 48) {
            int t = tid >> 4, c = tid & 15;
            const float* pl = al2 + (t * 16 + c) * 16;
            const float* pr = ar2 + (t * 16 + c) * 16;
            float s = 0.f;
#pragma unroll
            for (int j = 0; j < 16; j++) s += pl[j] + pr[j];
            u2s[tid] = s;
        }
        if (tid >= 240 && tid < 240 + C2) d_out[tid - 240] = 0.f;
        __syncthreads();
        if (tid < 192) {
            int t = tid >> 6, i = tid & 63;
            const float* w = W2 + (t * 64 + i) * 16;
            float s = 0.f;
#pragma unroll
            for (int c = 0; c < 16; c++) s = fmaf(w[c], u2s[t * 16 + c], s);
            g_v2[tid] = s;
        }
        return;
    }
    b -= 1;
    if (b < 16) {  // Wc: cols 0..47 = W2[t], cols 48..63 = res_w
        int i = b * 256 + tid;  // i = k*64 + c
        int k = i >> 6, c = i & 63;
        float v;
        if (c < 48) v = W2[(((c >> 4) * D1) + k) * C2 + (c & 15)];
        else        v = res_w[k * C2 + (c - 48)];
        g_Wc[i] = v;
        return;
    }
}

// ---------------- scan: smem-staged coalesced exclusive prefix ----------------
__global__ void k_scan() {  // single block, 1024 threads, NN*4 dynamic smem
    extern __shared__ int sdeg[];
    __shared__ int ss[1024];
    int tid = threadIdx.x;
    for (int i = tid; i < NN; i += 1024) sdeg[i] = g_deg[i];   // coalesced in
    __syncthreads();
    const int CH = 49;  // 1024*49 >= 50000
    int base = tid * CH;
    int s = 0;
    for (int i = 0; i < CH; i++) {
        int j = base + i;
        if (j < NN) s += sdeg[j];
    }
    ss[tid] = s;
    __syncthreads();
    for (int off = 1; off < 1024; off <<= 1) {
        int v = (tid >= off) ? ss[tid - off] : 0;
        __syncthreads();
        ss[tid] += v;
        __syncthreads();
    }
    if (tid == 1023) g_rowptr[NN] = ss[1023];
    int run = (tid > 0) ? ss[tid - 1] : 0;
    for (int i = 0; i < CH; i++) {  // in-place exclusive scan in smem
        int j = base + i;
        if (j < NN) {
            int d = sdeg[j];
            sdeg[j] = run;
            run += d;
        }
    }
    __syncthreads();
    for (int i = tid; i < NN; i += 1024) {  // coalesced out
        int v = sdeg[i];
        g_rowptr[i] = v;
        g_cursor[i] = v;
    }
}

// ---------------- scatter (ILP 4) + re-zero deg for next call ----------------
__global__ void k_scatter(const int* __restrict__ src, const int* __restrict__ dst,
                          const int* __restrict__ etype) {
    int t0 = blockIdx.x * 1024 + threadIdx.x;
#pragma unroll
    for (int k = 0; k < 4; k++) {
        int e = t0 + k * 256;
        if (e < EE) {
            int pos = atomicAdd(&g_cursor[dst[e]], 1);
            g_gather[pos] = src[e] * TT + etype[e];
        }
    }
    int gt = blockIdx.x * 256 + threadIdx.x;  // deg consumed by k_scan; reset now
    for (int i = gt; i < NN; i += gridDim.x * 256) g_deg[i] = 0;
}

// ---------------- GEMM micro-kernel: 4x4 tile, k chunked by 4, all-float4 LDS ----------------
// xs/ws: [64][68]; per 4-k chunk: 4 a-LDS.128 (contiguous along k) + 4 b-LDS.128.
#define GEMM_CORE(XS, WS, ACC, RR, CC)                                              \
    _Pragma("unroll")                                                               \
    for (int k4 = 0; k4 < 64; k4 += 4) {                                            \
        float4 a[4], bb[4];                                                         \
        a[0] = *reinterpret_cast<const float4*>(&XS[RR][k4]);                       \
        a[1] = *reinterpret_cast<const float4*>(&XS[RR + 1][k4]);                   \
        a[2] = *reinterpret_cast<const float4*>(&XS[RR + 2][k4]);                   \
        a[3] = *reinterpret_cast<const float4*>(&XS[RR + 3][k4]);                   \
        bb[0] = *reinterpret_cast<const float4*>(&WS[k4][CC]);                      \
        bb[1] = *reinterpret_cast<const float4*>(&WS[k4 + 1][CC]);                  \
        bb[2] = *reinterpret_cast<const float4*>(&WS[k4 + 2][CC]);                  \
        bb[3] = *reinterpret_cast<const float4*>(&WS[k4 + 3][CC]);                  \
        _Pragma("unroll")                                                           \
        for (int i = 0; i < 4; i++) {                                               \
            float av0 = a[i].x, av1 = a[i].y, av2 = a[i].z, av3 = a[i].w;           \
            ACC[i][0] = fmaf(av0, bb[0].x, ACC[i][0]);                              \
            ACC[i][1] = fmaf(av0, bb[0].y, ACC[i][1]);                              \
            ACC[i][2] = fmaf(av0, bb[0].z, ACC[i][2]);                              \
            ACC[i][3] = fmaf(av0, bb[0].w, ACC[i][3]);                              \
            ACC[i][0] = fmaf(av1, bb[1].x, ACC[i][0]);                              \
            ACC[i][1] = fmaf(av1, bb[1].y, ACC[i][1]);                              \
            ACC[i][2] = fmaf(av1, bb[1].z, ACC[i][2]);                              \
            ACC[i][3] = fmaf(av1, bb[1].w, ACC[i][3]);                              \
            ACC[i][0] = fmaf(av2, bb[2].x, ACC[i][0]);                              \
            ACC[i][1] = fmaf(av2, bb[2].y, ACC[i][1]);                              \
            ACC[i][2] = fmaf(av2, bb[2].z, ACC[i][2]);                              \
            ACC[i][3] = fmaf(av2, bb[2].w, ACC[i][3]);                              \
            ACC[i][0] = fmaf(av3, bb[3].x, ACC[i][0]);                              \
            ACC[i][1] = fmaf(av3, bb[3].y, ACC[i][1]);                              \
            ACC[i][2] = fmaf(av3, bb[3].z, ACC[i][2]);                              \
            ACC[i][3] = fmaf(av3, bb[3].w, ACC[i][3]);                              \
        }                                                                           \
    }

// ---------------- layer0 compute: y<3 -> feat1[n,t,:]=x@W1[t]; y==3 -> es1 ----------------
__global__ void __launch_bounds__(256) k_l1(const float* __restrict__ x,
                                            const float* __restrict__ W1) {
    __shared__ float xs[64][68];
    __shared__ float ws[64][68];
    int r0 = blockIdx.x * 64;
    int tid = threadIdx.x;
    // load x tile (common)
    for (int i = tid; i < 64 * 16; i += 256) {
        int r = i >> 4, c4 = (i & 15) << 2;
        float4 v = make_float4(0.f, 0.f, 0.f, 0.f);
        if (r0 + r < NN) v = *reinterpret_cast<const float4*>(x + (r0 + r) * 64 + c4);
        *reinterpret_cast<float4*>(&xs[r][c4]) = v;
    }
    if (blockIdx.y < 3) {
        int t = blockIdx.y;
        for (int i = tid; i < 64 * 16; i += 256) {
            int r = i >> 4, c4 = (i & 15) << 2;
            float4 w = *reinterpret_cast<const float4*>(W1 + (t * 64 + r) * 64 + c4);
            *reinterpret_cast<float4*>(&ws[r][c4]) = w;
        }
        __syncthreads();
        int cc = (tid & 15) << 2;
        int rr = (tid >> 4) << 2;
        float acc[4][4] = {};
        GEMM_CORE(xs, ws, acc, rr, cc)
#pragma unroll
        for (int i2 = 0; i2 < 4; i2++) {
            int r = r0 + rr + i2;
            if (r < NN) {
                float4 o = make_float4(acc[i2][0], acc[i2][1], acc[i2][2], acc[i2][3]);
                *reinterpret_cast<float4*>(&g_feat1[(r * TT + t) * 64 + cc]) = o;
            }
        }
    } else {
        // es1[n][t*8+h] = exp(leakyrelu( x[n,:] . v1[:, t*8+h] ))
        for (int i2 = tid; i2 < 64 * 24; i2 += 256) {
            int r = i2 / 24, c = i2 - r * 24;
            ws[r][c] = g_v1[i2];
        }
        __syncthreads();
        int row = tid >> 2;
        int c0 = (tid & 3) * 6;
        float s[6] = {0.f, 0.f, 0.f, 0.f, 0.f, 0.f};
#pragma unroll
        for (int i4 = 0; i4 < 64; i4 += 4) {
            float4 xv = *reinterpret_cast<const float4*>(&xs[row][i4]);
#pragma unroll
            for (int c = 0; c < 6; c++) {
                s[c] = fmaf(xv.x, ws[i4][c0 + c], s[c]);
                s[c] = fmaf(xv.y, ws[i4 + 1][c0 + c], s[c]);
                s[c] = fmaf(xv.z, ws[i4 + 2][c0 + c], s[c]);
                s[c] = fmaf(xv.w, ws[i4 + 3][c0 + c], s[c]);
            }
        }
        int n = r0 + row;
        if (n < NN) {
#pragma unroll
            for (int c = 0; c < 6; c++) {
                float a = s[c];
                a = a > 0.f ? a : 0.2f * a;
                g_es1[n * 24 + c0 + c] = expf(a);
            }
        }
    }
}

// ---------------- layer0 aggregation + fused layer1 score (es2) ----------------
__global__ void __launch_bounds__(256) k_agg1() {
    __shared__ float v2s[3][64];
    __shared__ float part[4][2][3];
    int tid = threadIdx.x;
    if (tid < 192) v2s[tid >> 6][tid & 63] = g_v2[tid];
    int node = blockIdx.x * 4 + (tid >> 6);
    int j = tid & 63;
    int h = j >> 3;
    float v = 0.f;
    if (node < NN) {
        int beg = g_rowptr[node], end = g_rowptr[node + 1];
        float acc = 0.f, wsum = 0.f;
        int p = beg;
        // 4-wide batches: independent index loads, then independent data loads (MLP=4)
        for (; p + 4 <= end; p += 4) {
            int g0 = __ldg(&g_gather[p]);
            int g1 = __ldg(&g_gather[p + 1]);
            int g2 = __ldg(&g_gather[p + 2]);
            int g3 = __ldg(&g_gather[p + 3]);
            float w0 = __ldg(&g_es1[g0 * 8 + h]);
            float w1 = __ldg(&g_es1[g1 * 8 + h]);
            float w2 = __ldg(&g_es1[g2 * 8 + h]);
            float w3 = __ldg(&g_es1[g3 * 8 + h]);
            float f0 = __ldg(&g_feat1[g0 * 64 + j]);
            float f1 = __ldg(&g_feat1[g1 * 64 + j]);
            float f2 = __ldg(&g_feat1[g2 * 64 + j]);
            float f3 = __ldg(&g_feat1[g3 * 64 + j]);
            acc = fmaf(f0, w0, acc);
            acc = fmaf(f1, w1, acc);
            acc = fmaf(f2, w2, acc);
            acc = fmaf(f3, w3, acc);
            wsum += (w0 + w1) + (w2 + w3);
        }
        for (; p < end; p++) {
            int g = __ldg(&g_gather[p]);
            float w = __ldg(&g_es1[g * 8 + h]);
            acc = fmaf(__ldg(&g_feat1[g * 64 + j]), w, acc);
            wsum += w;
        }
        v = (end > beg) ? acc / wsum : 0.f;
        v = v > 0.f ? v : (expf(v) - 1.f);  // ELU
        g_h[node * 64 + j] = v;
    }
    __syncthreads();  // v2s ready
    float p0 = v * v2s[0][j];
    float p1 = v * v2s[1][j];
    float p2 = v * v2s[2][j];
#pragma unroll
    for (int off = 16; off > 0; off >>= 1) {
        p0 += __shfl_down_sync(0xffffffffu, p0, off);
        p1 += __shfl_down_sync(0xffffffffu, p1, off);
        p2 += __shfl_down_sync(0xffffffffu, p2, off);
    }
    if ((tid & 31) == 0) {
        int nib = tid >> 6, wh = (tid >> 5) & 1;
        part[nib][wh][0] = p0;
        part[nib][wh][1] = p1;
        part[nib][wh][2] = p2;
    }
    __syncthreads();
    if (tid < 16) {
        int nib = tid >> 2, t = tid & 3;
        if (t < 3) {
            int nd = blockIdx.x * 4 + nib;
            if (nd < NN) {
                float s = part[nib][0][t] + part[nib][1][t];
                s = s > 0.f ? s : 0.2f * s;
                g_es2[nd * 3 + t] = expf(s);
            }
        }
    }
}

// ---------------- layer 1 GEMM: [feat2 | resid] = h @ Wc (+bias on resid cols) ----------------
__global__ void __launch_bounds__(256) k_feat2(const float* __restrict__ res_b) {
    __shared__ float xs[64][68];
    __shared__ float ws[64][68];
    int r0 = blockIdx.x * 64;
    int tid = threadIdx.x;
    for (int i = tid; i < 64 * 16; i += 256) {
        int r = i >> 4, c4 = (i & 15) << 2;
        float4 v = make_float4(0.f, 0.f, 0.f, 0.f);
        if (r0 + r < NN) v = *reinterpret_cast<const float4*>(g_h + (r0 + r) * 64 + c4);
        *reinterpret_cast<float4*>(&xs[r][c4]) = v;
        float4 w = *reinterpret_cast<const float4*>(g_Wc + r * 64 + c4);
        *reinterpret_cast<float4*>(&ws[r][c4]) = w;
    }
    __syncthreads();
    int cc = (tid & 15) << 2;
    int rr = (tid >> 4) << 2;
    float acc[4][4] = {};
    GEMM_CORE(xs, ws, acc, rr, cc)
#pragma unroll
    for (int i2 = 0; i2 < 4; i2++) {
        int r = r0 + rr + i2;
        if (r < NN) {
            if (cc < 48) {
                int t = cc >> 4;
                float4 o = make_float4(acc[i2][0], acc[i2][1], acc[i2][2], acc[i2][3]);
                *reinterpret_cast<float4*>(&g_feat2[(r * TT + t) * 16 + (cc & 15)]) = o;
            } else {
                int c0 = cc - 48;
                float4 o = make_float4(acc[i2][0] + res_b[c0], acc[i2][1] + res_b[c0 + 1],
                                       acc[i2][2] + res_b[c0 + 2], acc[i2][3] + res_b[c0 + 3]);
                *reinterpret_cast<float4*>(&g_resid[r * 16 + c0]) = o;
            }
        }
    }
}

// ---------------- layer1 aggregation + residual + mean pooling ----------------
__global__ void __launch_bounds__(256) k_agg2(float* __restrict__ d_out) {
    __shared__ float red[256];
    int node = blockIdx.x * 16 + (threadIdx.x >> 4);
    int j = threadIdx.x & 15;
    float val = 0.f;
    if (node < NN) {
        int beg = g_rowptr[node], end = g_rowptr[node + 1];
        float acc = 0.f, wsum = 0.f;
        int p = beg;
        for (; p + 4 <= end; p += 4) {
            int g0 = __ldg(&g_gather[p]);
            int g1 = __ldg(&g_gather[p + 1]);
            int g2 = __ldg(&g_gather[p + 2]);
            int g3 = __ldg(&g_gather[p + 3]);
            float w0 = __ldg(&g_es2[g0]);
            float w1 = __ldg(&g_es2[g1]);
            float w2 = __ldg(&g_es2[g2]);
            float w3 = __ldg(&g_es2[g3]);
            float f0 = __ldg(&g_feat2[g0 * 16 + j]);
            float f1 = __ldg(&g_feat2[g1 * 16 + j]);
            float f2 = __ldg(&g_feat2[g2 * 16 + j]);
            float f3 = __ldg(&g_feat2[g3 * 16 + j]);
            acc = fmaf(f0, w0, acc);
            acc = fmaf(f1, w1, acc);
            acc = fmaf(f2, w2, acc);
            acc = fmaf(f3, w3, acc);
            wsum += (w0 + w1) + (w2 + w3);
        }
        for (; p < end; p++) {
            int g = __ldg(&g_gather[p]);
            float w = __ldg(&g_es2[g]);
            acc = fmaf(__ldg(&g_feat2[g * 16 + j]), w, acc);
            wsum += w;
        }
        val = ((end > beg) ? acc / wsum : 0.f) + g_resid[node * 16 + j];
    }
    red[threadIdx.x] = val * (1.0f / NN);
    __syncthreads();
#pragma unroll
    for (int s = 8; s > 0; s >>= 1) {
        if ((threadIdx.x >> 4) < s) red[threadIdx.x] += red[threadIdx.x + s * 16];
        __syncthreads();
    }
    if (threadIdx.x < 16) atomicAdd(&d_out[threadIdx.x], red[threadIdx.x]);
}

// ---------------- launch ----------------
extern "C" void kernel_launch(void* const* d_in, const int* in_sizes, int n_in,
                              void* d_out, int out_size) {
    const float* x     = (const float*)d_in[0];
    const int*   src   = (const int*)d_in[1];
    const int*   dst   = (const int*)d_in[2];
    // d_in[3] = ntype (unused by reference math)
    const int*   etype = (const int*)d_in[4];
    const float* W1    = (const float*)d_in[5];
    const float* al1   = (const float*)d_in[6];
    const float* ar1   = (const float*)d_in[7];
    const float* W2    = (const float*)d_in[8];
    const float* al2   = (const float*)d_in[9];
    const float* ar2   = (const float*)d_in[10];
    const float* res_w = (const float*)d_in[11];
    const float* res_b = (const float*)d_in[12];
    float* out = (float*)d_out;

    cudaFuncSetAttribute(k_scan, cudaFuncAttributeMaxDynamicSharedMemorySize, NN * 4);

    k_setup<<<HIST_BLOCKS + TT + 1 + 16, 256>>>(al1, ar1, al2, ar2, W1, W2, res_w, dst, out);
    k_scan<<<1, 1024, NN * 4>>>();
    k_scatter<<<HIST_BLOCKS, 256>>>(src, dst, etype);
    k_l1<<<dim3((NN + 63) / 64, 4), 256>>>(x, W1);
    k_agg1<<<(NN + 3) / 4, 256>>>();
    k_feat2<<<(NN + 63) / 64, 256>>>(res_b);
    k_agg2<<<(NN + 15) / 16, 256>>>(out);
}

// round 6
// speedup vs baseline: 1.1052x; 1.1052x over previous
#include <cuda_runtime.h>

#define NN 50000
#define EE 800000
#define TT 3
#define HH 8
#define D1 64
#define C2 16

typedef unsigned long long u64;

// ---------------- scratch (static device globals; no allocation) ----------------
__device__ float g_feat1[NN * TT * D1];   // 38.4 MB per-(node,type) layer0 features
__device__ float g_es1[NN * TT * HH];     // 4.8 MB  exp(leakyrelu(score)) layer0, [n][t][h]
__device__ float g_h[NN * D1];            // 12.8 MB layer0 output
__device__ float g_feat2[NN * TT * C2];   // 9.6 MB
__device__ float g_es2[NN * TT];          // 0.6 MB  [n][t]
__device__ float g_resid[NN * C2];        // 3.2 MB  h@res_w + b
__device__ float g_v1[D1 * TT * HH];      // [i][t*8+h]
__device__ float g_v2[TT * D1];           // [t][i]
__device__ float g_Wc[D1 * 64];           // combined [W2(t=0..2) | res_w]
__device__ int   g_deg[NN];               // zero at load; re-zeroed by k_scatter tail
__device__ int   g_rowptr[NN + 1];
__device__ int   g_cursor[NN];
__device__ int   g_gather[EE];            // CSR payload: src*3 + etype

#define HIST_BLOCKS ((EE + 1023) / 1024)  // 782, 4 edges/thread

// ---------------- f32x2 packed-FMA helpers ----------------
__device__ __forceinline__ u64 pack2(float v) {
    u64 r;
    unsigned u = __float_as_uint(v);
    asm("mov.b64 %0, {%1, %1};" : "=l"(r) : "r"(u));
    return r;
}
__device__ __forceinline__ void ffma2(u64& d, u64 a, u64 b) {
    asm("fma.rn.f32x2 %0, %1, %2, %0;" : "+l"(d) : "l"(a), "l"(b));
}

#define GEMM_ROW(ACCR, AV, B0, B1, B2, B3) {                                        \
        u64 t_;                                                                     \
        t_ = pack2(AV.x); ffma2(ACCR[0], t_, B0.x); ffma2(ACCR[1], t_, B0.y);       \
        t_ = pack2(AV.y); ffma2(ACCR[0], t_, B1.x); ffma2(ACCR[1], t_, B1.y);       \
        t_ = pack2(AV.z); ffma2(ACCR[0], t_, B2.x); ffma2(ACCR[1], t_, B2.y);       \
        t_ = pack2(AV.w); ffma2(ACCR[0], t_, B3.x); ffma2(ACCR[1], t_, B3.y);       \
    }

// 4x4 micro-tile, k chunked by 4; b-side loads land directly as u64 pairs.
#define GEMM_CORE2(XS, WS, ACC2, RR, CC)                                            \
    _Pragma("unroll")                                                               \
    for (int k4 = 0; k4 < 64; k4 += 4) {                                            \
        float4 a0 = *reinterpret_cast<const float4*>(&XS[RR][k4]);                  \
        float4 a1 = *reinterpret_cast<const float4*>(&XS[RR + 1][k4]);              \
        float4 a2 = *reinterpret_cast<const float4*>(&XS[RR + 2][k4]);              \
        float4 a3 = *reinterpret_cast<const float4*>(&XS[RR + 3][k4]);              \
        ulonglong2 b0 = *reinterpret_cast<const ulonglong2*>(&WS[k4][CC]);          \
        ulonglong2 b1 = *reinterpret_cast<const ulonglong2*>(&WS[k4 + 1][CC]);      \
        ulonglong2 b2 = *reinterpret_cast<const ulonglong2*>(&WS[k4 + 2][CC]);      \
        ulonglong2 b3 = *reinterpret_cast<const ulonglong2*>(&WS[k4 + 3][CC]);      \
        GEMM_ROW(ACC2[0], a0, b0, b1, b2, b3)                                       \
        GEMM_ROW(ACC2[1], a1, b0, b1, b2, b3)                                       \
        GEMM_ROW(ACC2[2], a2, b0, b1, b2, b3)                                       \
        GEMM_ROW(ACC2[3], a3, b0, b1, b2, b3)                                       \
    }

// ---------------- setup: hist + zero d_out + build v1/v2/Wc ----------------
__global__ void k_setup(const float* __restrict__ al1, const float* __restrict__ ar1,
                        const float* __restrict__ al2, const float* __restrict__ ar2,
                        const float* __restrict__ W1, const float* __restrict__ W2,
                        const float* __restrict__ res_w, const int* __restrict__ dst,
                        float* __restrict__ d_out) {
    int b = blockIdx.x;
    int tid = threadIdx.x;
    if (b < HIST_BLOCKS) {
        int t0 = b * 1024 + tid;
#pragma unroll
        for (int k = 0; k < 4; k++) {
            int e = t0 + k * 256;
            if (e < EE) atomicAdd(&g_deg[dst[e]], 1);
        }
        return;
    }
    b -= HIST_BLOCKS;
    if (b < TT) {  // v1 for type t=b
        int t = b;
        __shared__ float u1s[64][8];
        for (int e = tid; e < 512; e += 256) {
            int c = e >> 3, h = e & 7;
            const float* pl = al1 + t * 4096 + c * 64 + h * 8;
            const float* pr = ar1 + t * 4096 + c * 64 + h * 8;
            float s = 0.f;
#pragma unroll
            for (int d = 0; d < 8; d++) s += pl[d] + pr[d];
            u1s[c][h] = s;
        }
        __syncthreads();
        for (int e = tid; e < 512; e += 256) {
            int i = e >> 3, h = e & 7;
            const float* w = W1 + t * 4096 + i * 64;
            float s = 0.f;
#pragma unroll 8
            for (int c = 0; c < 64; c++) s = fmaf(w[c], u1s[c][h], s);
            g_v1[i * 24 + t * 8 + h] = s;
        }
        return;
    }
    b -= TT;
    if (b < 1) {  // v2 + zero d_out
        __shared__ float u2s[48];
        if (tid < 48) {
            int t = tid >> 4, c = tid & 15;
            const float* pl = al2 + (t * 16 + c) * 16;
            const float* pr = ar2 + (t * 16 + c) * 16;
            float s = 0.f;
#pragma unroll
            for (int j = 0; j < 16; j++) s += pl[j] + pr[j];
            u2s[tid] = s;
        }
        if (tid >= 240 && tid < 240 + C2) d_out[tid - 240] = 0.f;
        __syncthreads();
        if (tid < 192) {
            int t = tid >> 6, i = tid & 63;
            const float* w = W2 + (t * 64 + i) * 16;
            float s = 0.f;
#pragma unroll
            for (int c = 0; c < 16; c++) s = fmaf(w[c], u2s[t * 16 + c], s);
            g_v2[tid] = s;
        }
        return;
    }
    b -= 1;
    if (b < 16) {  // Wc
        int i = b * 256 + tid;
        int k = i >> 6, c = i & 63;
        float v;
        if (c < 48) v = W2[(((c >> 4) * D1) + k) * C2 + (c & 15)];
        else        v = res_w[k * C2 + (c - 48)];
        g_Wc[i] = v;
        return;
    }
}

// ---------------- scan ----------------
__global__ void k_scan() {
    extern __shared__ int sdeg[];
    __shared__ int ss[1024];
    int tid = threadIdx.x;
    for (int i = tid; i < NN; i += 1024) sdeg[i] = g_deg[i];
    __syncthreads();
    const int CH = 49;
    int base = tid * CH;
    int s = 0;
    for (int i = 0; i < CH; i++) {
        int j = base + i;
        if (j < NN) s += sdeg[j];
    }
    ss[tid] = s;
    __syncthreads();
    for (int off = 1; off < 1024; off <<= 1) {
        int v = (tid >= off) ? ss[tid - off] : 0;
        __syncthreads();
        ss[tid] += v;
        __syncthreads();
    }
    if (tid == 1023) g_rowptr[NN] = ss[1023];
    int run = (tid > 0) ? ss[tid - 1] : 0;
    for (int i = 0; i < CH; i++) {
        int j = base + i;
        if (j < NN) {
            int d = sdeg[j];
            sdeg[j] = run;
            run += d;
        }
    }
    __syncthreads();
    for (int i = tid; i < NN; i += 1024) {
        int v = sdeg[i];
        g_rowptr[i] = v;
        g_cursor[i] = v;
    }
}

// ---------------- scatter ----------------
__global__ void k_scatter(const int* __restrict__ src, const int* __restrict__ dst,
                          const int* __restrict__ etype) {
    int t0 = blockIdx.x * 1024 + threadIdx.x;
#pragma unroll
    for (int k = 0; k < 4; k++) {
        int e = t0 + k * 256;
        if (e < EE) {
            int pos = atomicAdd(&g_cursor[dst[e]], 1);
            g_gather[pos] = src[e] * TT + etype[e];
        }
    }
    int gt = blockIdx.x * 256 + threadIdx.x;
    for (int i = gt; i < NN; i += gridDim.x * 256) g_deg[i] = 0;
}

// ---------------- layer0: y<3 -> feat1 GEMM (f32x2); y==3 -> es1 ----------------
__global__ void __launch_bounds__(256) k_l1(const float* __restrict__ x,
                                            const float* __restrict__ W1) {
    __shared__ float xs[64][68];
    __shared__ float ws[64][68];
    int r0 = blockIdx.x * 64;
    int tid = threadIdx.x;
    for (int i = tid; i < 64 * 16; i += 256) {
        int r = i >> 4, c4 = (i & 15) << 2;
        float4 v = make_float4(0.f, 0.f, 0.f, 0.f);
        if (r0 + r < NN) v = *reinterpret_cast<const float4*>(x + (r0 + r) * 64 + c4);
        *reinterpret_cast<float4*>(&xs[r][c4]) = v;
    }
    if (blockIdx.y < 3) {
        int t = blockIdx.y;
        for (int i = tid; i < 64 * 16; i += 256) {
            int r = i >> 4, c4 = (i & 15) << 2;
            float4 w = *reinterpret_cast<const float4*>(W1 + (t * 64 + r) * 64 + c4);
            *reinterpret_cast<float4*>(&ws[r][c4]) = w;
        }
        __syncthreads();
        int cc = (tid & 15) << 2;
        int rr = (tid >> 4) << 2;
        u64 acc2[4][2] = {};
        GEMM_CORE2(xs, ws, acc2, rr, cc)
#pragma unroll
        for (int i2 = 0; i2 < 4; i2++) {
            int r = r0 + rr + i2;
            if (r < NN) {
                float2 lo = *reinterpret_cast<float2*>(&acc2[i2][0]);
                float2 hi = *reinterpret_cast<float2*>(&acc2[i2][1]);
                float4 o = make_float4(lo.x, lo.y, hi.x, hi.y);
                *reinterpret_cast<float4*>(&g_feat1[(r * TT + t) * 64 + cc]) = o;
            }
        }
    } else {
        // es1[n][t*8+h] = exp(leakyrelu( x[n,:] . v1[:, t*8+h] ))
        for (int i2 = tid; i2 < 64 * 24; i2 += 256) {
            int r = i2 / 24, c = i2 - r * 24;
            ws[r][c] = g_v1[i2];
        }
        __syncthreads();
        int row = tid >> 2;
        int c0 = (tid & 3) * 6;
        float s[6] = {0.f, 0.f, 0.f, 0.f, 0.f, 0.f};
#pragma unroll
        for (int i4 = 0; i4 < 64; i4 += 4) {
            float4 xv = *reinterpret_cast<const float4*>(&xs[row][i4]);
#pragma unroll
            for (int c = 0; c < 6; c++) {
                s[c] = fmaf(xv.x, ws[i4][c0 + c], s[c]);
                s[c] = fmaf(xv.y, ws[i4 + 1][c0 + c], s[c]);
                s[c] = fmaf(xv.z, ws[i4 + 2][c0 + c], s[c]);
                s[c] = fmaf(xv.w, ws[i4 + 3][c0 + c], s[c]);
            }
        }
        int n = r0 + row;
        if (n < NN) {
#pragma unroll
            for (int c = 0; c < 6; c++) {
                float a = s[c];
                a = a > 0.f ? a : 0.2f * a;
                g_es1[n * 24 + c0 + c] = expf(a);
            }
        }
    }
}

// ---------------- layer0 aggregation: warp-per-node, float2 lanes ----------------
__global__ void __launch_bounds__(256) k_agg1() {
    __shared__ float v2s[3][64];
    int tid = threadIdx.x;
    if (tid < 192) v2s[tid >> 6][tid & 63] = g_v2[tid];
    __syncthreads();
    int warp = tid >> 5, lane = tid & 31;
    int node = blockIdx.x * 8 + warp;
    if (node >= NN) return;
    int beg = g_rowptr[node], end = g_rowptr[node + 1];
    int j2 = lane * 2;
    int h = lane >> 2;  // cols 2j,2j+1 share head h = (2*lane)>>3
    float ax = 0.f, ay = 0.f, wsum = 0.f;
    int p = beg;
    for (; p + 4 <= end; p += 4) {
        int g0 = __ldg(&g_gather[p]);
        int g1 = __ldg(&g_gather[p + 1]);
        int g2 = __ldg(&g_gather[p + 2]);
        int g3 = __ldg(&g_gather[p + 3]);
        float w0 = __ldg(&g_es1[g0 * 8 + h]);
        float w1 = __ldg(&g_es1[g1 * 8 + h]);
        float w2 = __ldg(&g_es1[g2 * 8 + h]);
        float w3 = __ldg(&g_es1[g3 * 8 + h]);
        float2 f0 = __ldg(reinterpret_cast<const float2*>(&g_feat1[g0 * 64 + j2]));
        float2 f1 = __ldg(reinterpret_cast<const float2*>(&g_feat1[g1 * 64 + j2]));
        float2 f2 = __ldg(reinterpret_cast<const float2*>(&g_feat1[g2 * 64 + j2]));
        float2 f3 = __ldg(reinterpret_cast<const float2*>(&g_feat1[g3 * 64 + j2]));
        ax = fmaf(f0.x, w0, ax); ay = fmaf(f0.y, w0, ay);
        ax = fmaf(f1.x, w1, ax); ay = fmaf(f1.y, w1, ay);
        ax = fmaf(f2.x, w2, ax); ay = fmaf(f2.y, w2, ay);
        ax = fmaf(f3.x, w3, ax); ay = fmaf(f3.y, w3, ay);
        wsum += (w0 + w1) + (w2 + w3);
    }
    for (; p < end; p++) {
        int g = __ldg(&g_gather[p]);
        float w = __ldg(&g_es1[g * 8 + h]);
        float2 f = __ldg(reinterpret_cast<const float2*>(&g_feat1[g * 64 + j2]));
        ax = fmaf(f.x, w, ax); ay = fmaf(f.y, w, ay);
        wsum += w;
    }
    float vx = 0.f, vy = 0.f;
    if (end > beg) {
        vx = ax / wsum;
        vy = ay / wsum;
    }
    vx = vx > 0.f ? vx : (expf(vx) - 1.f);  // ELU
    vy = vy > 0.f ? vy : (expf(vy) - 1.f);
    float2 vo = make_float2(vx, vy);
    *reinterpret_cast<float2*>(&g_h[node * 64 + j2]) = vo;
    // fused layer-1 scores: es2[node][t] = exp(leakyrelu( h[node,:] . v2[t] ))
    float p0 = vx * v2s[0][j2] + vy * v2s[0][j2 + 1];
    float p1 = vx * v2s[1][j2] + vy * v2s[1][j2 + 1];
    float p2 = vx * v2s[2][j2] + vy * v2s[2][j2 + 1];
#pragma unroll
    for (int off = 16; off > 0; off >>= 1) {
        p0 += __shfl_down_sync(0xffffffffu, p0, off);
        p1 += __shfl_down_sync(0xffffffffu, p1, off);
        p2 += __shfl_down_sync(0xffffffffu, p2, off);
    }
    if (lane == 0) {
        float s0 = p0 > 0.f ? p0 : 0.2f * p0;
        float s1 = p1 > 0.f ? p1 : 0.2f * p1;
        float s2 = p2 > 0.f ? p2 : 0.2f * p2;
        g_es2[node * 3 + 0] = expf(s0);
        g_es2[node * 3 + 1] = expf(s1);
        g_es2[node * 3 + 2] = expf(s2);
    }
}

// ---------------- layer 1 GEMM (f32x2): [feat2 | resid] = h @ Wc ----------------
__global__ void __launch_bounds__(256) k_feat2(const float* __restrict__ res_b) {
    __shared__ float xs[64][68];
    __shared__ float ws[64][68];
    int r0 = blockIdx.x * 64;
    int tid = threadIdx.x;
    for (int i = tid; i < 64 * 16; i += 256) {
        int r = i >> 4, c4 = (i & 15) << 2;
        float4 v = make_float4(0.f, 0.f, 0.f, 0.f);
        if (r0 + r < NN) v = *reinterpret_cast<const float4*>(g_h + (r0 + r) * 64 + c4);
        *reinterpret_cast<float4*>(&xs[r][c4]) = v;
        float4 w = *reinterpret_cast<const float4*>(g_Wc + r * 64 + c4);
        *reinterpret_cast<float4*>(&ws[r][c4]) = w;
    }
    __syncthreads();
    int cc = (tid & 15) << 2;
    int rr = (tid >> 4) << 2;
    u64 acc2[4][2] = {};
    GEMM_CORE2(xs, ws, acc2, rr, cc)
#pragma unroll
    for (int i2 = 0; i2 < 4; i2++) {
        int r = r0 + rr + i2;
        if (r < NN) {
            float2 lo = *reinterpret_cast<float2*>(&acc2[i2][0]);
            float2 hi = *reinterpret_cast<float2*>(&acc2[i2][1]);
            if (cc < 48) {
                int t = cc >> 4;
                float4 o = make_float4(lo.x, lo.y, hi.x, hi.y);
                *reinterpret_cast<float4*>(&g_feat2[(r * TT + t) * 16 + (cc & 15)]) = o;
            } else {
                int c0 = cc - 48;
                float4 o = make_float4(lo.x + res_b[c0], lo.y + res_b[c0 + 1],
                                       hi.x + res_b[c0 + 2], hi.y + res_b[c0 + 3]);
                *reinterpret_cast<float4*>(&g_resid[r * 16 + c0]) = o;
            }
        }
    }
}

// ---------------- layer1 aggregation + residual + mean pooling ----------------
// 8 threads per node (float2 lanes), 32 nodes per block.
__global__ void __launch_bounds__(256) k_agg2(float* __restrict__ d_out) {
    __shared__ float2 red[256];
    int tid = threadIdx.x;
    int grp = tid >> 3;          // node-in-block 0..31
    int j = tid & 7;             // cols 2j, 2j+1
    int node = blockIdx.x * 32 + grp;
    float2 val = make_float2(0.f, 0.f);
    if (node < NN) {
        int beg = g_rowptr[node], end = g_rowptr[node + 1];
        float ax = 0.f, ay = 0.f, wsum = 0.f;
        int p = beg;
        for (; p + 4 <= end; p += 4) {
            int g0 = __ldg(&g_gather[p]);
            int g1 = __ldg(&g_gather[p + 1]);
            int g2 = __ldg(&g_gather[p + 2]);
            int g3 = __ldg(&g_gather[p + 3]);
            float w0 = __ldg(&g_es2[g0]);
            float w1 = __ldg(&g_es2[g1]);
            float w2 = __ldg(&g_es2[g2]);
            float w3 = __ldg(&g_es2[g3]);
            float2 f0 = __ldg(reinterpret_cast<const float2*>(&g_feat2[g0 * 16 + j * 2]));
            float2 f1 = __ldg(reinterpret_cast<const float2*>(&g_feat2[g1 * 16 + j * 2]));
            float2 f2 = __ldg(reinterpret_cast<const float2*>(&g_feat2[g2 * 16 + j * 2]));
            float2 f3 = __ldg(reinterpret_cast<const float2*>(&g_feat2[g3 * 16 + j * 2]));
            ax = fmaf(f0.x, w0, ax); ay = fmaf(f0.y, w0, ay);
            ax = fmaf(f1.x, w1, ax); ay = fmaf(f1.y, w1, ay);
            ax = fmaf(f2.x, w2, ax); ay = fmaf(f2.y, w2, ay);
            ax = fmaf(f3.x, w3, ax); ay = fmaf(f3.y, w3, ay);
            wsum += (w0 + w1) + (w2 + w3);
        }
        for (; p < end; p++) {
            int g = __ldg(&g_gather[p]);
            float w = __ldg(&g_es2[g]);
            float2 f = __ldg(reinterpret_cast<const float2*>(&g_feat2[g * 16 + j * 2]));
            ax = fmaf(f.x, w, ax); ay = fmaf(f.y, w, ay);
            wsum += w;
        }
        float2 rs = *reinterpret_cast<const float2*>(&g_resid[node * 16 + j * 2]);
        val.x = ((end > beg) ? ax / wsum : 0.f) + rs.x;
        val.y = ((end > beg) ? ay / wsum : 0.f) + rs.y;
    }
    val.x *= (1.0f / NN);
    val.y *= (1.0f / NN);
    red[tid] = val;
    __syncthreads();
#pragma unroll
    for (int s = 16; s > 0; s >>= 1) {
        if (grp < s) {
            float2 o = red[tid + s * 8];
            red[tid].x += o.x;
            red[tid].y += o.y;
        }
        __syncthreads();
    }
    if (tid < 8) {
        atomicAdd(&d_out[tid * 2], red[tid].x);
        atomicAdd(&d_out[tid * 2 + 1], red[tid].y);
    }
}

// ---------------- launch ----------------
extern "C" void kernel_launch(void* const* d_in, const int* in_sizes, int n_in,
                              void* d_out, int out_size) {
    const float* x     = (const float*)d_in[0];
    const int*   src   = (const int*)d_in[1];
    const int*   dst   = (const int*)d_in[2];
    // d_in[3] = ntype (unused by reference math)
    const int*   etype = (const int*)d_in[4];
    const float* W1    = (const float*)d_in[5];
    const float* al1   = (const float*)d_in[6];
    const float* ar1   = (const float*)d_in[7];
    const float* W2    = (const float*)d_in[8];
    const float* al2   = (const float*)d_in[9];
    const float* ar2   = (const float*)d_in[10];
    const float* res_w = (const float*)d_in[11];
    const float* res_b = (const float*)d_in[12];
    float* out = (float*)d_out;

    cudaFuncSetAttribute(k_scan, cudaFuncAttributeMaxDynamicSharedMemorySize, NN * 4);

    k_setup<<<HIST_BLOCKS + TT + 1 + 16, 256>>>(al1, ar1, al2, ar2, W1, W2, res_w, dst, out);
    k_scan<<<1, 1024, NN * 4>>>();
    k_scatter<<<HIST_BLOCKS, 256>>>(src, dst, etype);
    k_l1<<<dim3((NN + 63) / 64, 4), 256>>>(x, W1);
    k_agg1<<<(NN + 7) / 8, 256>>>();
    k_feat2<<<(NN + 63) / 64, 256>>>(res_b);
    k_agg2<<<(NN + 31) / 32, 256>>>(out);
}